// round 1
// baseline (speedup 1.0000x reference)
#include <cuda_runtime.h>

#define NN   40000
#define NE   640000
#define DIM  128
#define NDEC 64
#define TOT  (NN*DIM)
#define HALFT (TOT/2)

// JAX threefry counter scheme:
// 0 = original (pre-partitionable), 1 = partitionable w0^w1, 2 = partitionable w0, 3 = partitionable w1
#define SCHEME 1

__device__ float g_h[TOT];
__device__ float g_acc[TOT];
__device__ float g_deg[NN];
__device__ float g_loss;

__host__ __device__ __forceinline__ void tf2x32(unsigned k0, unsigned k1,
                                                unsigned x0, unsigned x1,
                                                unsigned &o0, unsigned &o1) {
  unsigned ks2 = k0 ^ k1 ^ 0x1BD11BDAu;
  x0 += k0; x1 += k1;
#define TFROT(x,r) (((x)<<(r))|((x)>>(32-(r))))
#define TFR(r) { x0 += x1; x1 = TFROT(x1,(r)); x1 ^= x0; }
  TFR(13) TFR(15) TFR(26) TFR(6)
  x0 += k1;  x1 += ks2 + 1u;
  TFR(17) TFR(29) TFR(16) TFR(24)
  x0 += ks2; x1 += k0 + 2u;
  TFR(13) TFR(15) TFR(26) TFR(6)
  x0 += k0;  x1 += k1 + 3u;
  TFR(17) TFR(29) TFR(16) TFR(24)
  x0 += k1;  x1 += ks2 + 4u;
  TFR(13) TFR(15) TFR(26) TFR(6)
  x0 += ks2; x1 += k0 + 5u;
  o0 = x0; o1 = x1;
#undef TFR
#undef TFROT
}

__device__ __forceinline__ bool keep_elem(unsigned k0, unsigned k1, unsigned j) {
#if SCHEME == 0
  unsigned w0, w1;
  if (j < HALFT) { tf2x32(k0,k1,j,j+HALFT,w0,w1); return (w0 & 0x80000000u) == 0u; }
  tf2x32(k0,k1,j-HALFT,j,w0,w1);
  return (w1 & 0x80000000u) == 0u;
#else
  unsigned w0, w1;
  tf2x32(k0,k1,0u,j,w0,w1);
#if SCHEME == 1
  unsigned bits = w0 ^ w1;
#elif SCHEME == 2
  unsigned bits = w0;
#else
  unsigned bits = w1;
#endif
  return (bits & 0x80000000u) == 0u;
#endif
}

__global__ void init_kernel() {
  int i = blockIdx.x*blockDim.x + threadIdx.x;
  if (i < NN) g_deg[i] = 1.0f;      // deg + 1 baked in
  if (i == 0) g_loss = 0.0f;
}

__global__ void deg_kernel(const int* __restrict__ dst) {
  int e = blockIdx.x*blockDim.x + threadIdx.x;
  if (e < NE) atomicAdd(&g_deg[dst[e]], 1.0f);
}

// dropout: h = keep ? 2*in : 0 ; also seeds acc = h (the +h_v self term)
__global__ void drop_kernel(const float* __restrict__ in, unsigned k0, unsigned k1) {
  unsigned j = blockIdx.x*blockDim.x + threadIdx.x;
  if (j >= (unsigned)TOT) return;
  float v = keep_elem(k0,k1,j) ? 2.0f*__ldg(&in[j]) : 0.0f;
  g_h[j] = v;
  g_acc[j] = v;
}

// one warp per edge: acc[dst] += h[src] (128 floats = 32 lanes x float4)
__global__ void edge_kernel(const int* __restrict__ src, const int* __restrict__ dst) {
  int e = blockIdx.x*8 + (threadIdx.x >> 5);
  int lane = threadIdx.x & 31;
  if (e >= NE) return;
  int s = __ldg(&src[e]);
  int d = __ldg(&dst[e]);
  const float4* hp = (const float4*)g_h;
  float4 v = __ldg(&hp[s*32 + lane]);
  atomicAdd(((float4*)g_acc) + (d*32 + lane), v);  // sm_90+ vector reduction
}

// out[i] = relu?((acc[i]/deg[i]) @ W^T + b)  ; 32 nodes per block, 4x4 register tile
__global__ void __launch_bounds__(256) gemm_kernel(const float* __restrict__ W,
                                                   const float* __restrict__ b,
                                                   float* __restrict__ out, int relu) {
  extern __shared__ float s[];
  float* sW = s;              // transposed [k][j], stride 132 (pad: conflict-free f4 reads)
  float* sA = s + DIM*132;    // [32][128]
  int tid = threadIdx.x;
  int i0 = blockIdx.x * 32;
  for (int idx = tid; idx < DIM*DIM; idx += 256) {
    int j = idx >> 7, k = idx & 127;
    sW[k*132 + j] = W[idx];
  }
  for (int idx = tid; idx < 32*DIM; idx += 256) {
    int r = idx >> 7;
    sA[idx] = g_acc[(i0+r)*DIM + (idx & 127)] / g_deg[i0+r];
  }
  __syncthreads();
  int rg = tid >> 5, cg = tid & 31;
  float acc4[4][4];
#pragma unroll
  for (int r=0;r<4;r++)
#pragma unroll
    for (int c=0;c<4;c++) acc4[r][c]=0.f;
  const float* sArow = sA + rg*4*DIM;
  for (int kk = 0; kk < DIM; kk += 4) {
    float a[4][4];
#pragma unroll
    for (int r=0;r<4;r++) {
      float4 t = *(const float4*)(sArow + r*DIM + kk);
      a[r][0]=t.x; a[r][1]=t.y; a[r][2]=t.z; a[r][3]=t.w;
    }
#pragma unroll
    for (int u=0;u<4;u++) {
      float4 wv = *(const float4*)(sW + (kk+u)*132 + cg*4);
#pragma unroll
      for (int r=0;r<4;r++) {
        acc4[r][0] = fmaf(a[r][u], wv.x, acc4[r][0]);
        acc4[r][1] = fmaf(a[r][u], wv.y, acc4[r][1]);
        acc4[r][2] = fmaf(a[r][u], wv.z, acc4[r][2]);
        acc4[r][3] = fmaf(a[r][u], wv.w, acc4[r][3]);
      }
    }
  }
  int colb = cg*4;
  float4 bb = *(const float4*)(b + colb);
#pragma unroll
  for (int r=0;r<4;r++) {
    int row = i0 + rg*4 + r;
    float4 v;
    v.x = acc4[r][0]+bb.x; v.y = acc4[r][1]+bb.y;
    v.z = acc4[r][2]+bb.z; v.w = acc4[r][3]+bb.w;
    if (relu) { v.x=fmaxf(v.x,0.f); v.y=fmaxf(v.y,0.f); v.z=fmaxf(v.z,0.f); v.w=fmaxf(v.w,0.f); }
    *(float4*)(out + (size_t)row*DIM + colb) = v;
  }
}

// one warp per node: h_a = h[i]@Wd^T+bd ; h_b = h[shuf[i]]@Wd^T+bd ; loss += sum h_b*(lse - h_a)
__global__ void __launch_bounds__(256) dec_kernel(const float* __restrict__ h,
                                                  const int* __restrict__ shuf,
                                                  const float* __restrict__ Wd,
                                                  const float* __restrict__ bd) {
  __shared__ float sW[DIM*66];   // packed: sW[k*66 + 2*(j&31) + (j>>5)] = Wd[j][k]
  __shared__ float sbd[NDEC];
  __shared__ float srow[8][DIM];
  __shared__ float wsum[8];
  int tid = threadIdx.x;
  for (int idx = tid; idx < NDEC*DIM; idx += 256) {
    int j = idx >> 7, k = idx & 127;
    sW[k*66 + ((j&31)<<1) + (j>>5)] = Wd[idx];
  }
  if (tid < NDEC) sbd[tid] = bd[tid];
  __syncthreads();
  int w = tid >> 5, l = tid & 31;
  int node = blockIdx.x*8 + w;

  ((float4*)srow[w])[l] = ((const float4*)(h + (size_t)node*DIM))[l];
  __syncwarp();
  float ha0 = sbd[l], ha1 = sbd[l+32];
  for (int kk=0; kk<DIM; kk+=4) {
    float4 a = *(const float4*)(srow[w]+kk);
    const float* wp = sW + kk*66 + (l<<1);
    float2 q0 = *(const float2*)(wp);
    float2 q1 = *(const float2*)(wp+66);
    float2 q2 = *(const float2*)(wp+132);
    float2 q3 = *(const float2*)(wp+198);
    ha0 = fmaf(a.x,q0.x, fmaf(a.y,q1.x, fmaf(a.z,q2.x, fmaf(a.w,q3.x, ha0))));
    ha1 = fmaf(a.x,q0.y, fmaf(a.y,q1.y, fmaf(a.z,q2.y, fmaf(a.w,q3.y, ha1))));
  }
  float m = fmaxf(ha0, ha1);
#pragma unroll
  for (int o=16;o;o>>=1) m = fmaxf(m, __shfl_xor_sync(0xffffffffu, m, o));
  float es = expf(ha0-m) + expf(ha1-m);
#pragma unroll
  for (int o=16;o;o>>=1) es += __shfl_xor_sync(0xffffffffu, es, o);
  float lse = m + logf(es);

  int node2 = __ldg(&shuf[node]);
  __syncwarp();
  ((float4*)srow[w])[l] = ((const float4*)(h + (size_t)node2*DIM))[l];
  __syncwarp();
  float hb0 = sbd[l], hb1 = sbd[l+32];
  for (int kk=0; kk<DIM; kk+=4) {
    float4 a = *(const float4*)(srow[w]+kk);
    const float* wp = sW + kk*66 + (l<<1);
    float2 q0 = *(const float2*)(wp);
    float2 q1 = *(const float2*)(wp+66);
    float2 q2 = *(const float2*)(wp+132);
    float2 q3 = *(const float2*)(wp+198);
    hb0 = fmaf(a.x,q0.x, fmaf(a.y,q1.x, fmaf(a.z,q2.x, fmaf(a.w,q3.x, hb0))));
    hb1 = fmaf(a.x,q0.y, fmaf(a.y,q1.y, fmaf(a.z,q2.y, fmaf(a.w,q3.y, hb1))));
  }
  float part = hb0*(lse-ha0) + hb1*(lse-ha1);
#pragma unroll
  for (int o=16;o;o>>=1) part += __shfl_xor_sync(0xffffffffu, part, o);
  if (l == 0) wsum[w] = part;
  __syncthreads();
  if (tid == 0) {
    float s2 = 0.f;
#pragma unroll
    for (int i=0;i<8;i++) s2 += wsum[i];
    atomicAdd(&g_loss, s2);
  }
}

__global__ void fin_kernel(float* out, int idx) {
  out[idx] = g_loss * (1.0f/(float)NN);
}

extern "C" void kernel_launch(void* const* d_in, const int* in_sizes, int n_in,
                              void* d_out, int out_size) {
  const float* x  = (const float*)d_in[0];
  const int* src  = (const int*)d_in[1];
  const int* dst  = (const int*)d_in[2];
  const int* shuf = (const int*)d_in[3];
  const float* W1 = (const float*)d_in[4];
  const float* b1 = (const float*)d_in[5];
  const float* W2 = (const float*)d_in[6];
  const float* b2 = (const float*)d_in[7];
  const float* Wd = (const float*)d_in[8];
  const float* bd = (const float*)d_in[9];
  float* out = (float*)d_out;

  // host-side child key derivation: dk = jax.random.split(key(42), 2)
  unsigned dk0a, dk0b, dk1a, dk1b;
#if SCHEME == 0
  { unsigned a0,a1,c0,c1;
    tf2x32(0u,42u,0u,2u,a0,a1);
    tf2x32(0u,42u,1u,3u,c0,c1);
    dk0a=a0; dk0b=c0; dk1a=a1; dk1b=c1; }
#else
  tf2x32(0u,42u,0u,0u,dk0a,dk0b);
  tf2x32(0u,42u,0u,1u,dk1a,dk1b);
#endif

  float* hptr = nullptr;
  cudaGetSymbolAddress((void**)&hptr, g_h);

  const int smem_gemm = (DIM*132 + 32*DIM)*(int)sizeof(float);
  cudaFuncSetAttribute(gemm_kernel, cudaFuncAttributeMaxDynamicSharedMemorySize, smem_gemm);

  init_kernel<<<(NN+255)/256, 256>>>();
  deg_kernel<<<(NE+255)/256, 256>>>(dst);

  // layer 1
  drop_kernel<<<TOT/256, 256>>>(x, dk0a, dk0b);
  edge_kernel<<<NE/8, 256>>>(src, dst);
  gemm_kernel<<<NN/32, 256, smem_gemm>>>(W1, b1, hptr, 1);

  // layer 2
  drop_kernel<<<TOT/256, 256>>>(hptr, dk1a, dk1b);
  edge_kernel<<<NE/8, 256>>>(src, dst);
  gemm_kernel<<<NN/32, 256, smem_gemm>>>(W2, b2, out, 0);

  // decoder
  dec_kernel<<<NN/8, 256>>>(out, shuf, Wd, bd);
  fin_kernel<<<1,1>>>(out, out_size - 1);
}

// round 4
// speedup vs baseline: 1.5206x; 1.5206x over previous
#include <cuda_runtime.h>

#define NN   40000
#define NE   640000
#define DIM  128
#define NDEC 64
#define TOT  (NN*DIM)
#define NPART 157          // ceil(NN/256)

__device__ float g_h[TOT];
__device__ float g_acc[TOT];
__device__ float g_logits[NN*NDEC];
__device__ int   g_ptr[NN+1];
__device__ int   g_cur[NN];
__device__ int   g_part[NPART];
__device__ int   g_csrc[NE];
__device__ float g_loss;

__host__ __device__ __forceinline__ void tf2x32(unsigned k0, unsigned k1,
                                                unsigned x0, unsigned x1,
                                                unsigned &o0, unsigned &o1) {
  unsigned ks2 = k0 ^ k1 ^ 0x1BD11BDAu;
  x0 += k0; x1 += k1;
#define TFROT(x,r) (((x)<<(r))|((x)>>(32-(r))))
#define TFR(r) { x0 += x1; x1 = TFROT(x1,(r)); x1 ^= x0; }
  TFR(13) TFR(15) TFR(26) TFR(6)
  x0 += k1;  x1 += ks2 + 1u;
  TFR(17) TFR(29) TFR(16) TFR(24)
  x0 += ks2; x1 += k0 + 2u;
  TFR(13) TFR(15) TFR(26) TFR(6)
  x0 += k0;  x1 += k1 + 3u;
  TFR(17) TFR(29) TFR(16) TFR(24)
  x0 += k1;  x1 += ks2 + 4u;
  TFR(13) TFR(15) TFR(26) TFR(6)
  x0 += ks2; x1 += k0 + 5u;
  o0 = x0; o1 = x1;
#undef TFR
#undef TFROT
}

__device__ __forceinline__ bool keep_elem(unsigned k0, unsigned k1, unsigned j) {
  unsigned w0, w1;
  tf2x32(k0, k1, 0u, j, w0, w1);
  return ((w0 ^ w1) & 0x80000000u) == 0u;
}

// ---------- CSR build ----------
__global__ void zero_kernel() {
  int i = blockIdx.x*blockDim.x + threadIdx.x;
  if (i < NN) g_cur[i] = 0;
  if (i == 0) g_loss = 0.0f;
}

__global__ void hist_kernel(const int* __restrict__ dst) {
  int e = blockIdx.x*blockDim.x + threadIdx.x;
  if (e < NE) atomicAdd(&g_cur[dst[e]], 1);
}

__global__ void scan1_kernel() {
  __shared__ int sh[256];
  int t = threadIdx.x;
  int i = blockIdx.x*256 + t;
  int v = (i < NN) ? g_cur[i] : 0;
  sh[t] = v; __syncthreads();
#pragma unroll
  for (int off = 1; off < 256; off <<= 1) {
    int a = (t >= off) ? sh[t-off] : 0;
    __syncthreads();
    sh[t] += a; __syncthreads();
  }
  if (i < NN) g_ptr[i] = sh[t] - v;          // exclusive within block
  if (t == 255) g_part[blockIdx.x] = sh[255];
}

__global__ void scan2_kernel() {
  __shared__ int sh[256];
  int t = threadIdx.x;
  int v = (t < NPART) ? g_part[t] : 0;
  sh[t] = v; __syncthreads();
#pragma unroll
  for (int off = 1; off < 256; off <<= 1) {
    int a = (t >= off) ? sh[t-off] : 0;
    __syncthreads();
    sh[t] += a; __syncthreads();
  }
  if (t < NPART) g_part[t] = sh[t] - v;      // exclusive over blocks
}

__global__ void scan3_kernel() {
  int i = blockIdx.x*256 + threadIdx.x;
  if (i < NN) {
    int p = g_ptr[i] + g_part[blockIdx.x];
    g_ptr[i] = p;
    g_cur[i] = p;
  }
  if (i == 0) g_ptr[NN] = NE;
}

__global__ void scatter_kernel(const int* __restrict__ src, const int* __restrict__ dst) {
  int e = blockIdx.x*blockDim.x + threadIdx.x;
  if (e >= NE) return;
  int slot = atomicAdd(&g_cur[dst[e]], 1);
  g_csrc[slot] = src[e];
}

// ---------- dropout ----------
__global__ void drop_kernel(const float* __restrict__ in, unsigned k0, unsigned k1) {
  unsigned j = blockIdx.x*blockDim.x + threadIdx.x;
  if (j >= (unsigned)TOT) return;
  g_h[j] = keep_elem(k0, k1, j) ? 2.0f*__ldg(&in[j]) : 0.0f;
}

// ---------- pull-based aggregation: acc[i] = (h[i] + sum_{u->i} h[u]) / (deg+1) ----------
__global__ void __launch_bounds__(256) gather_kernel() {
  int node = blockIdx.x*8 + (threadIdx.x >> 5);
  int lane = threadIdx.x & 31;
  int beg = g_ptr[node], end = g_ptr[node+1];
  const float4* hp = (const float4*)g_h;
  float4 acc = __ldg(&hp[node*32 + lane]);   // self term
  int k = beg;
  for (; k + 4 <= end; k += 4) {
    int s0 = g_csrc[k], s1 = g_csrc[k+1], s2 = g_csrc[k+2], s3 = g_csrc[k+3];
    float4 v0 = __ldg(&hp[s0*32 + lane]);
    float4 v1 = __ldg(&hp[s1*32 + lane]);
    float4 v2 = __ldg(&hp[s2*32 + lane]);
    float4 v3 = __ldg(&hp[s3*32 + lane]);
    acc.x += (v0.x + v1.x) + (v2.x + v3.x);
    acc.y += (v0.y + v1.y) + (v2.y + v3.y);
    acc.z += (v0.z + v1.z) + (v2.z + v3.z);
    acc.w += (v0.w + v1.w) + (v2.w + v3.w);
  }
  for (; k < end; k++) {
    float4 v = __ldg(&hp[g_csrc[k]*32 + lane]);
    acc.x += v.x; acc.y += v.y; acc.z += v.z; acc.w += v.w;
  }
  float inv = 1.0f / (float)(end - beg + 1);
  acc.x *= inv; acc.y *= inv; acc.z *= inv; acc.w *= inv;
  ((float4*)g_acc)[node*32 + lane] = acc;
}

// ---------- GEMM: out = in @ W^T + b, optional relu, optional fused dropout ----------
__global__ void __launch_bounds__(256) gemm_kernel(const float* __restrict__ W,
                                                   const float* __restrict__ b,
                                                   float* __restrict__ out,
                                                   int relu, int dodrop,
                                                   unsigned k0, unsigned k1) {
  extern __shared__ float s[];
  float* sW = s;              // transposed [k][j], stride 132
  float* sA = s + DIM*132;    // [32][128]
  int tid = threadIdx.x;
  int i0 = blockIdx.x * 32;
  for (int idx = tid; idx < DIM*DIM; idx += 256) {
    int j = idx >> 7, kk = idx & 127;
    sW[kk*132 + j] = W[idx];
  }
  for (int idx = tid; idx < 32*DIM; idx += 256)
    sA[idx] = g_acc[i0*DIM + idx];
  __syncthreads();
  int rg = tid >> 5, cg = tid & 31;
  float acc4[4][4];
#pragma unroll
  for (int r = 0; r < 4; r++)
#pragma unroll
    for (int c = 0; c < 4; c++) acc4[r][c] = 0.f;
  const float* sArow = sA + rg*4*DIM;
  for (int kk = 0; kk < DIM; kk += 4) {
    float a[4][4];
#pragma unroll
    for (int r = 0; r < 4; r++) {
      float4 t = *(const float4*)(sArow + r*DIM + kk);
      a[r][0]=t.x; a[r][1]=t.y; a[r][2]=t.z; a[r][3]=t.w;
    }
#pragma unroll
    for (int u = 0; u < 4; u++) {
      float4 wv = *(const float4*)(sW + (kk+u)*132 + cg*4);
#pragma unroll
      for (int r = 0; r < 4; r++) {
        acc4[r][0] = fmaf(a[r][u], wv.x, acc4[r][0]);
        acc4[r][1] = fmaf(a[r][u], wv.y, acc4[r][1]);
        acc4[r][2] = fmaf(a[r][u], wv.z, acc4[r][2]);
        acc4[r][3] = fmaf(a[r][u], wv.w, acc4[r][3]);
      }
    }
  }
  int colb = cg*4;
  float4 bb = *(const float4*)(b + colb);
#pragma unroll
  for (int r = 0; r < 4; r++) {
    int row = i0 + rg*4 + r;
    float v[4];
    v[0] = acc4[r][0]+bb.x; v[1] = acc4[r][1]+bb.y;
    v[2] = acc4[r][2]+bb.z; v[3] = acc4[r][3]+bb.w;
    if (relu) {
#pragma unroll
      for (int c = 0; c < 4; c++) v[c] = fmaxf(v[c], 0.f);
    }
    if (dodrop) {
      unsigned base = (unsigned)row*DIM + colb;
#pragma unroll
      for (int c = 0; c < 4; c++)
        v[c] = keep_elem(k0, k1, base + c) ? 2.0f*v[c] : 0.0f;
    }
    *(float4*)(out + (size_t)row*DIM + colb) = make_float4(v[0],v[1],v[2],v[3]);
  }
}

// ---------- decoder logits: L = h @ Wd^T + bd  (32 nodes/block, 4x2 tiles) ----------
__global__ void __launch_bounds__(256) logits_kernel(const float* __restrict__ h,
                                                     const float* __restrict__ Wd,
                                                     const float* __restrict__ bd) {
  extern __shared__ float s[];
  float* sW = s;             // [k][j], stride 66 (even: float2 stays 8B-aligned)
  float* sA = s + DIM*66;    // [32][128]
  int tid = threadIdx.x;
  int i0 = blockIdx.x * 32;
  for (int idx = tid; idx < NDEC*DIM; idx += 256) {
    int j = idx >> 7, kk = idx & 127;
    sW[kk*66 + j] = Wd[idx];
  }
  for (int idx = tid; idx < 32*DIM; idx += 256)
    sA[idx] = h[(size_t)i0*DIM + idx];
  __syncthreads();
  int rg = tid >> 5, cg = tid & 31;   // rows rg*4..+3, cols cg*2..+1
  float a0 = 0.f, a1 = 0.f, a2 = 0.f, a3 = 0.f;
  float b0 = 0.f, b1 = 0.f, b2 = 0.f, b3 = 0.f;
  const float* sArow = sA + rg*4*DIM;
  int colb = cg*2;
  for (int kk = 0; kk < DIM; kk += 2) {
    float2 w0 = *(const float2*)(sW + kk*66 + colb);
    float2 w1 = *(const float2*)(sW + (kk+1)*66 + colb);
    float2 x0 = *(const float2*)(sArow + 0*DIM + kk);
    float2 x1 = *(const float2*)(sArow + 1*DIM + kk);
    float2 x2 = *(const float2*)(sArow + 2*DIM + kk);
    float2 x3 = *(const float2*)(sArow + 3*DIM + kk);
    a0 = fmaf(x0.x, w0.x, fmaf(x0.y, w1.x, a0));
    b0 = fmaf(x0.x, w0.y, fmaf(x0.y, w1.y, b0));
    a1 = fmaf(x1.x, w0.x, fmaf(x1.y, w1.x, a1));
    b1 = fmaf(x1.x, w0.y, fmaf(x1.y, w1.y, b1));
    a2 = fmaf(x2.x, w0.x, fmaf(x2.y, w1.x, a2));
    b2 = fmaf(x2.x, w0.y, fmaf(x2.y, w1.y, b2));
    a3 = fmaf(x3.x, w0.x, fmaf(x3.y, w1.x, a3));
    b3 = fmaf(x3.x, w0.y, fmaf(x3.y, w1.y, b3));
  }
  float2 bb = *(const float2*)(bd + colb);
  float* L = g_logits;
  int r0 = i0 + rg*4;
  *(float2*)(L + (size_t)(r0+0)*NDEC + colb) = make_float2(a0+bb.x, b0+bb.y);
  *(float2*)(L + (size_t)(r0+1)*NDEC + colb) = make_float2(a1+bb.x, b1+bb.y);
  *(float2*)(L + (size_t)(r0+2)*NDEC + colb) = make_float2(a2+bb.x, b2+bb.y);
  *(float2*)(L + (size_t)(r0+3)*NDEC + colb) = make_float2(a3+bb.x, b3+bb.y);
}

// ---------- loss: sum_i sum_j L[shuf[i]][j] * (lse(L[i]) - L[i][j]) ----------
__global__ void __launch_bounds__(256) loss_kernel(const int* __restrict__ shuf) {
  __shared__ float wsum[8];
  int tid = threadIdx.x;
  int w = tid >> 5, l = tid & 31;
  int node = blockIdx.x*8 + w;
  float2 a = *(const float2*)(g_logits + (size_t)node*NDEC + l*2);
  float m = fmaxf(a.x, a.y);
#pragma unroll
  for (int o = 16; o; o >>= 1) m = fmaxf(m, __shfl_xor_sync(0xffffffffu, m, o));
  float es = expf(a.x - m) + expf(a.y - m);
#pragma unroll
  for (int o = 16; o; o >>= 1) es += __shfl_xor_sync(0xffffffffu, es, o);
  float lse = m + logf(es);
  int s = __ldg(&shuf[node]);
  float2 b = *(const float2*)(g_logits + (size_t)s*NDEC + l*2);
  float part = b.x*(lse - a.x) + b.y*(lse - a.y);
#pragma unroll
  for (int o = 16; o; o >>= 1) part += __shfl_xor_sync(0xffffffffu, part, o);
  if (l == 0) wsum[w] = part;
  __syncthreads();
  if (tid == 0) {
    float s2 = 0.f;
#pragma unroll
    for (int i = 0; i < 8; i++) s2 += wsum[i];
    atomicAdd(&g_loss, s2);
  }
}

__global__ void fin_kernel(float* out, int idx) {
  out[idx] = g_loss * (1.0f/(float)NN);
}

extern "C" void kernel_launch(void* const* d_in, const int* in_sizes, int n_in,
                              void* d_out, int out_size) {
  const float* x  = (const float*)d_in[0];
  const int* src  = (const int*)d_in[1];
  const int* dst  = (const int*)d_in[2];
  const int* shuf = (const int*)d_in[3];
  const float* W1 = (const float*)d_in[4];
  const float* b1 = (const float*)d_in[5];
  const float* W2 = (const float*)d_in[6];
  const float* b2 = (const float*)d_in[7];
  const float* Wd = (const float*)d_in[8];
  const float* bd = (const float*)d_in[9];
  float* out = (float*)d_out;

  // dk = jax.random.split(key(42), 2): child i = threefry(key, (0, i))
  unsigned dk0a, dk0b, dk1a, dk1b;
  tf2x32(0u, 42u, 0u, 0u, dk0a, dk0b);
  tf2x32(0u, 42u, 0u, 1u, dk1a, dk1b);

  float* hptr = nullptr;
  cudaGetSymbolAddress((void**)&hptr, g_h);

  const int smem_gemm = (DIM*132 + 32*DIM)*(int)sizeof(float);
  const int smem_log  = (DIM*66 + 32*DIM)*(int)sizeof(float);
  cudaFuncSetAttribute(gemm_kernel, cudaFuncAttributeMaxDynamicSharedMemorySize, smem_gemm);
  cudaFuncSetAttribute(logits_kernel, cudaFuncAttributeMaxDynamicSharedMemorySize, smem_log);

  // CSR build
  zero_kernel<<<NPART, 256>>>();
  hist_kernel<<<NE/256, 256>>>(dst);
  scan1_kernel<<<NPART, 256>>>();
  scan2_kernel<<<1, 256>>>();
  scan3_kernel<<<NPART, 256>>>();
  scatter_kernel<<<NE/256, 256>>>(src, dst);

  // layer 1: dropout(x) -> gather -> gemm(+relu +dropout2 fused) -> g_h
  drop_kernel<<<TOT/256, 256>>>(x, dk0a, dk0b);
  gather_kernel<<<NN/8, 256>>>();
  gemm_kernel<<<NN/32, 256, smem_gemm>>>(W1, b1, hptr, 1, 1, dk1a, dk1b);

  // layer 2: gather -> gemm -> out
  gather_kernel<<<NN/8, 256>>>();
  gemm_kernel<<<NN/32, 256, smem_gemm>>>(W2, b2, out, 0, 0, 0u, 0u);

  // decoder
  logits_kernel<<<NN/32, 256, smem_log>>>(out, Wd, bd);
  loss_kernel<<<NN/8, 256>>>(shuf);
  fin_kernel<<<1, 1>>>(out, out_size - 1);
}